// round 13
// baseline (speedup 1.0000x reference)
#include <cuda_runtime.h>
#include <cuda_bf16.h>

// GCN: 4 layers, N=100000, dims 64->32->16->8->64, E=3,200,000.
// conv(y) = D^-1/2 Â D^-1/2 (y@W) + b,  Â = A + I.
// Factored: h' = (y@W)·dinv ; raw = Â h' ; z = raw·dinv + b.
// Layer 4 via linearity: out = (Â(relu(z3)·dinv))·dinv @ W4 + b4.
//
// GEMMs fused into agg epilogues; cross-lane row exchange via SMEM staging
// (STS.128 + syncwarp + broadcast LDS.128) instead of shuffles (32 SHFL/thread
// measured as the fusion overhead). agg32 pull loop is ~90% of the LTS cap.
//
// edge_index dtype detected on device (JAX silently downcasts int64->int32).

#define N_NODES 100000
#define N_EDGES 3200000
#define CAP     128      // max in-edges per node (deg~Poisson(32))

// ---------------- scratch (static device globals; no allocation) ----------------
__device__ __align__(16) int   g_csr[(size_t)N_NODES * CAP];
__device__ __align__(16) int   g_cnt[N_NODES];
__device__ int                 g_is_i32;
__device__ __align__(16) float g_bufA[N_NODES * 32];
__device__ __align__(16) float g_bufB[N_NODES * 32];

static inline int cdiv(long long a, int b) { return (int)((a + b - 1) / b); }

__device__ __forceinline__ float node_dinv(int n) {
    return rsqrtf((float)g_cnt[n] + 1.0f);   // +1 self loop
}

// ---------------- prep: cnt=0 + dtype detect ----------------
__global__ void init_detect_kernel(const long long* __restrict__ ei64) {
    unsigned i = blockIdx.x * blockDim.x + threadIdx.x;
    if (i < N_NODES) g_cnt[i] = 0;
    if (blockIdx.x == 0) {
        __shared__ int bad;
        if (threadIdx.x == 0) bad = 0;
        __syncthreads();
        for (int k = threadIdx.x; k < 2048; k += blockDim.x) {
            long long v = ei64[k];
            if (v < 0 || v >= N_NODES) bad = 1;   // benign race
        }
        __syncthreads();
        if (threadIdx.x == 0) g_is_i32 = bad;
    }
}

// ---------------- prep: bin edges into padded CSR (4 edges/thread) ----------
__global__ void prep_fill_kernel(const void* __restrict__ ei_raw) {
    unsigned t = blockIdx.x * blockDim.x + threadIdx.x;
    unsigned e0 = t * 4;
    if (e0 >= N_EDGES) return;
    int s[4], d[4];
    if (g_is_i32) {
        const int* ei = (const int*)ei_raw;
        int4 sv = *(const int4*)(ei + e0);
        int4 dv = *(const int4*)(ei + N_EDGES + e0);
        s[0]=sv.x; s[1]=sv.y; s[2]=sv.z; s[3]=sv.w;
        d[0]=dv.x; d[1]=dv.y; d[2]=dv.z; d[3]=dv.w;
    } else {
        const long long* ei = (const long long*)ei_raw;
#pragma unroll
        for (int q = 0; q < 4; q++) {
            s[q] = (int)ei[e0 + q];
            d[q] = (int)ei[N_EDGES + e0 + q];
        }
    }
#pragma unroll
    for (int q = 0; q < 4; q++) {
        int ss = s[q] & 0x7fffffff; if (ss >= N_NODES) ss %= N_NODES;
        int dd = d[q] & 0x7fffffff; if (dd >= N_NODES) dd %= N_NODES;
        int slot = atomicAdd(&g_cnt[dd], 1);
        if (slot < CAP) g_csr[(size_t)dd * CAP + slot] = ss;
    }
}

// ---------------- gemm1: h1' = (x@W1)·dinv  (64 -> 32, thread-per-node) -------
__global__ void gemm1_kernel(const float* __restrict__ in,
                             const float* __restrict__ W,
                             float* __restrict__ hout) {
    __shared__ float Ws[64 * 32];
    for (int i = threadIdx.x; i < 64 * 32; i += blockDim.x) Ws[i] = W[i];
    __syncthreads();

    int node = blockIdx.x * blockDim.x + threadIdx.x;
    if (node >= N_NODES) return;
    float dinv = node_dinv(node);

    float4 s4[8];
#pragma unroll
    for (int q = 0; q < 8; q++) s4[q] = make_float4(0.f, 0.f, 0.f, 0.f);

    const float4* row = (const float4*)(in + (size_t)node * 64);
    const float4* W4p = (const float4*)Ws;
#pragma unroll
    for (int c = 0; c < 16; c++) {
        float4 r = row[c];
        float a[4] = {r.x, r.y, r.z, r.w};
#pragma unroll
        for (int q = 0; q < 4; q++) {
            int k = 4 * c + q;
            float av = a[q];
#pragma unroll
            for (int j = 0; j < 8; j++) {
                float4 w = W4p[k * 8 + j];
                s4[j].x = fmaf(av, w.x, s4[j].x);
                s4[j].y = fmaf(av, w.y, s4[j].y);
                s4[j].z = fmaf(av, w.z, s4[j].z);
                s4[j].w = fmaf(av, w.w, s4[j].w);
            }
        }
    }
    float4* outv = (float4*)(hout + (size_t)node * 32);
#pragma unroll
    for (int q = 0; q < 8; q++) {
        s4[q].x *= dinv; s4[q].y *= dinv; s4[q].z *= dinv; s4[q].w *= dinv;
        outv[q] = s4[q];
    }
}

// ---------------- shared agg core: raw = h[node] + sum h[src] ----------------
template <int TPE>
__device__ __forceinline__ float4 agg_pull(const float4* __restrict__ h,
                                           int node, int j) {
    float4 acc = h[(size_t)node * TPE + j];        // self loop
    int n = g_cnt[node];
    if (n > CAP) n = CAP;
    const int* lst = g_csr + (size_t)node * CAP;   // 16B aligned
    int i = 0;
    for (; i + 4 <= n; i += 4) {
        int4 a4 = *(const int4*)(lst + i);
        float4 v0 = h[(size_t)a4.x * TPE + j];
        float4 v1 = h[(size_t)a4.y * TPE + j];
        float4 v2 = h[(size_t)a4.z * TPE + j];
        float4 v3 = h[(size_t)a4.w * TPE + j];
        acc.x += (v0.x + v1.x) + (v2.x + v3.x);
        acc.y += (v0.y + v1.y) + (v2.y + v3.y);
        acc.z += (v0.z + v1.z) + (v2.z + v3.z);
        acc.w += (v0.w + v1.w) + (v2.w + v3.w);
    }
    for (; i < n; i++) {
        int s = __ldg(&lst[i]);
        float4 v = h[(size_t)s * TPE + j];
        acc.x += v.x; acc.y += v.y; acc.z += v.z; acc.w += v.w;
    }
    return acc;
}

// ---- agg32 + gemm2: h2' = relu(Agg(h1')·dinv + b1)@W2 · dinv  (-> 16-dim) ----
__global__ void agg_gemm2_kernel(const float4* __restrict__ h,
                                 float* __restrict__ h2,
                                 const float* __restrict__ b1,
                                 const float* __restrict__ W2) {
    __shared__ float Ws[32 * 16];
    __shared__ float bs[32];
    __shared__ float4 zsm[256];                    // per-thread z staging
    for (int i = threadIdx.x; i < 32 * 16; i += blockDim.x) Ws[i] = W2[i];
    if (threadIdx.x < 32) bs[threadIdx.x] = b1[threadIdx.x];
    __syncthreads();

    unsigned gid = blockIdx.x * blockDim.x + threadIdx.x;
    if (gid >= (unsigned)N_NODES * 8) return;      // 800000 % 256 == 0: all active
    int node = gid >> 3;
    int j    = gid & 7;

    float4 acc = agg_pull<8>(h, node, j);
    float dinv = node_dinv(node);
    float4 z;
    z.x = fmaxf(fmaf(acc.x, dinv, bs[4 * j + 0]), 0.f);
    z.y = fmaxf(fmaf(acc.y, dinv, bs[4 * j + 1]), 0.f);
    z.z = fmaxf(fmaf(acc.z, dinv, bs[4 * j + 2]), 0.f);
    z.w = fmaxf(fmaf(acc.w, dinv, bs[4 * j + 3]), 0.f);

    zsm[threadIdx.x] = z;                          // STS.128
    __syncwarp();                                  // producers are in this warp

    int gbase = threadIdx.x & ~7;                  // group start (8 lanes/node)
    float o0 = 0.f, o1 = 0.f;
    int c0 = 2 * j, c1 = 2 * j + 1;
#pragma unroll
    for (int g = 0; g < 8; g++) {
        float4 zb = zsm[gbase + g];                // broadcast LDS.128
        int k = 4 * g;
        o0 = fmaf(zb.x, Ws[(k + 0) * 16 + c0], o0);
        o1 = fmaf(zb.x, Ws[(k + 0) * 16 + c1], o1);
        o0 = fmaf(zb.y, Ws[(k + 1) * 16 + c0], o0);
        o1 = fmaf(zb.y, Ws[(k + 1) * 16 + c1], o1);
        o0 = fmaf(zb.z, Ws[(k + 2) * 16 + c0], o0);
        o1 = fmaf(zb.z, Ws[(k + 2) * 16 + c1], o1);
        o0 = fmaf(zb.w, Ws[(k + 3) * 16 + c0], o0);
        o1 = fmaf(zb.w, Ws[(k + 3) * 16 + c1], o1);
    }
    *(float2*)(h2 + (size_t)node * 16 + c0) = make_float2(o0 * dinv, o1 * dinv);
}

// ---- agg16 + gemm3: h3' = relu(Agg(h2')·dinv + b2)@W3 · dinv  (-> 8-dim) ----
__global__ void agg_gemm3_kernel(const float4* __restrict__ h,
                                 float* __restrict__ h3,
                                 const float* __restrict__ b2,
                                 const float* __restrict__ W3) {
    __shared__ float Ws[16 * 8];
    __shared__ float bs[16];
    __shared__ float4 zsm[256];
    for (int i = threadIdx.x; i < 16 * 8; i += blockDim.x) Ws[i] = W3[i];
    if (threadIdx.x < 16) bs[threadIdx.x] = b2[threadIdx.x];
    __syncthreads();

    unsigned gid = blockIdx.x * blockDim.x + threadIdx.x;
    if (gid >= (unsigned)N_NODES * 4) return;      // 400000 % 32 == 0: warp-uniform
    int node = gid >> 2;
    int j    = gid & 3;

    float4 acc = agg_pull<4>(h, node, j);
    float dinv = node_dinv(node);
    float4 z;
    z.x = fmaxf(fmaf(acc.x, dinv, bs[4 * j + 0]), 0.f);
    z.y = fmaxf(fmaf(acc.y, dinv, bs[4 * j + 1]), 0.f);
    z.z = fmaxf(fmaf(acc.z, dinv, bs[4 * j + 2]), 0.f);
    z.w = fmaxf(fmaf(acc.w, dinv, bs[4 * j + 3]), 0.f);

    zsm[threadIdx.x] = z;
    __syncwarp();

    int gbase = threadIdx.x & ~3;                  // group start (4 lanes/node)
    float o0 = 0.f, o1 = 0.f;
    int c0 = 2 * j, c1 = 2 * j + 1;
#pragma unroll
    for (int g = 0; g < 4; g++) {
        float4 zb = zsm[gbase + g];
        int k = 4 * g;
        o0 = fmaf(zb.x, Ws[(k + 0) * 8 + c0], o0);
        o1 = fmaf(zb.x, Ws[(k + 0) * 8 + c1], o1);
        o0 = fmaf(zb.y, Ws[(k + 1) * 8 + c0], o0);
        o1 = fmaf(zb.y, Ws[(k + 1) * 8 + c1], o1);
        o0 = fmaf(zb.z, Ws[(k + 2) * 8 + c0], o0);
        o1 = fmaf(zb.z, Ws[(k + 2) * 8 + c1], o1);
        o0 = fmaf(zb.w, Ws[(k + 3) * 8 + c0], o0);
        o1 = fmaf(zb.w, Ws[(k + 3) * 8 + c1], o1);
    }
    *(float2*)(h3 + (size_t)node * 8 + c0) = make_float2(o0 * dinv, o1 * dinv);
}

// ---- agg8 + seed: h4' = relu(Agg(h3')·dinv + b3) · dinv  (-> 8-dim) ----
__global__ void agg_seed_kernel(const float4* __restrict__ h,
                                float4* __restrict__ h4,
                                const float* __restrict__ b3) {
    unsigned gid = blockIdx.x * blockDim.x + threadIdx.x;
    if (gid >= (unsigned)N_NODES * 2) return;      // 200000 % 32 == 0
    int node = gid >> 1;
    int j    = gid & 1;

    float4 acc = agg_pull<2>(h, node, j);
    float dinv = node_dinv(node);
    float4 bv = *(const float4*)(b3 + 4 * j);
    float4 o;
    o.x = fmaxf(fmaf(acc.x, dinv, bv.x), 0.f) * dinv;
    o.y = fmaxf(fmaf(acc.y, dinv, bv.y), 0.f) * dinv;
    o.z = fmaxf(fmaf(acc.z, dinv, bv.z), 0.f) * dinv;
    o.w = fmaxf(fmaf(acc.w, dinv, bv.w), 0.f) * dinv;
    h4[gid] = o;
}

// ---- agg8 + gemm4: out = (Agg(h4')·dinv)@W4 + b4  (-> 64-dim, d_out) ----
__global__ void agg_final_kernel(const float4* __restrict__ h,
                                 float* __restrict__ out,
                                 const float* __restrict__ W4,
                                 const float* __restrict__ b4) {
    __shared__ float Ws[8 * 64];
    __shared__ float bs[64];
    __shared__ float4 zsm[256];
    for (int i = threadIdx.x; i < 8 * 64; i += blockDim.x) Ws[i] = W4[i];
    if (threadIdx.x < 64) bs[threadIdx.x] = b4[threadIdx.x];
    __syncthreads();

    unsigned gid = blockIdx.x * blockDim.x + threadIdx.x;
    if (gid >= (unsigned)N_NODES * 2) return;      // warp-uniform
    int node = gid >> 1;
    int j    = gid & 1;

    float4 acc = agg_pull<2>(h, node, j);
    float dinv = node_dinv(node);
    float4 z;                                       // own K chunk, scaled
    z.x = acc.x * dinv; z.y = acc.y * dinv; z.z = acc.z * dinv; z.w = acc.w * dinv;

    zsm[threadIdx.x] = z;
    __syncwarp();

    int gbase = threadIdx.x & ~1;
    float4 z0 = zsm[gbase + 0];                     // k = 0..3
    float4 z1 = zsm[gbase + 1];                     // k = 4..7
    float zf[8] = {z0.x, z0.y, z0.z, z0.w, z1.x, z1.y, z1.z, z1.w};

    // lane j computes output columns [32j, 32j+32)
    int cbase = 32 * j;
    float4 s4[8];
    const float4* bsv = (const float4*)(bs + cbase);
#pragma unroll
    for (int q = 0; q < 8; q++) s4[q] = bsv[q];

#pragma unroll
    for (int k = 0; k < 8; k++) {
        float av = zf[k];
        const float4* wrow = (const float4*)(Ws + k * 64 + cbase);
#pragma unroll
        for (int q = 0; q < 8; q++) {
            float4 w = wrow[q];
            s4[q].x = fmaf(av, w.x, s4[q].x);
            s4[q].y = fmaf(av, w.y, s4[q].y);
            s4[q].z = fmaf(av, w.z, s4[q].z);
            s4[q].w = fmaf(av, w.w, s4[q].w);
        }
    }
    float4* outv = (float4*)(out + (size_t)node * 64 + cbase);
#pragma unroll
    for (int q = 0; q < 8; q++) outv[q] = s4[q];
}

// ---------------- launch ----------------
extern "C" void kernel_launch(void* const* d_in, const int* in_sizes, int n_in,
                              void* d_out, int out_size) {
    const float* x  = (const float*)d_in[0];
    const float* W1 = (const float*)d_in[2];
    const float* b1 = (const float*)d_in[3];
    const float* W2 = (const float*)d_in[4];
    const float* b2 = (const float*)d_in[5];
    const float* W3 = (const float*)d_in[6];
    const float* b3 = (const float*)d_in[7];
    const float* W4 = (const float*)d_in[8];
    const float* b4 = (const float*)d_in[9];
    float* out = (float*)d_out;

    float *A, *B;
    cudaGetSymbolAddress((void**)&A, g_bufA);
    cudaGetSymbolAddress((void**)&B, g_bufB);
    float4* A4 = (float4*)A;
    float4* B4 = (float4*)B;

    const int T = 256;

    // prep
    init_detect_kernel<<<cdiv(N_NODES, T), T>>>((const long long*)d_in[1]);
    prep_fill_kernel<<<cdiv(N_EDGES / 4, T), T>>>(d_in[1]);

    // conv1 gemm: A = (x@W1)·dinv   (32-dim)
    gemm1_kernel<<<cdiv(N_NODES, 128), 128>>>(x, W1, A);
    // conv1 agg + conv2 gemm: B = h2'  (16-dim)
    agg_gemm2_kernel<<<cdiv((long long)N_NODES * 8, T), T>>>(A4, B, b1, W2);
    // conv2 agg + conv3 gemm: A = h3'  (8-dim)
    agg_gemm3_kernel<<<cdiv((long long)N_NODES * 4, T), T>>>(B4, A, b2, W3);
    // conv3 agg + relu seed:  B = h4'  (8-dim)
    agg_seed_kernel<<<cdiv((long long)N_NODES * 2, T), T>>>(A4, B4, b3);
    // conv4 agg + final gemm: out      (64-dim)
    agg_final_kernel<<<cdiv((long long)N_NODES * 2, T), T>>>(B4, out, W4, b4);
}